// round 12
// baseline (speedup 1.0000x reference)
#include <cuda_runtime.h>
#include <cuda_pipeline.h>
#include <cstdint>

// Problem constants
#define BB 2
#define TT 4096
#define CC 512
#define HH 8
#define DD 64
#define MEMW 256

// Scratch (allocation-free rule: device globals)
__device__ float g_qkv[(size_t)BB * TT * 3 * CC];  // 50.3 MB
__device__ float g_y[(size_t)BB * TT * CC];        // 16.8 MB

__device__ __forceinline__ unsigned f2tf(float x) {
    unsigned r;
    asm("cvt.rna.tf32.f32 %0, %1;" : "=r"(r) : "f"(x));
    return r;
}

__device__ __forceinline__ void mma8(float* d, const unsigned* a, const unsigned* b) {
    asm volatile(
        "mma.sync.aligned.m16n8k8.row.col.f32.tf32.tf32.f32 "
        "{%0,%1,%2,%3},{%4,%5,%6,%7},{%8,%9},{%0,%1,%2,%3};\n"
        : "+f"(d[0]), "+f"(d[1]), "+f"(d[2]), "+f"(d[3])
        : "r"(a[0]), "r"(a[1]), "r"(a[2]), "r"(a[3]), "r"(b[0]), "r"(b[1]));
}

// ---------------------------------------------------------------------------
// GEMM: C[M,N] = A[M,K] * B[N,K]^T   (A row-major MxK, B row-major NxK)
// Block tile 128x128, k-tile 16, cp.async double buffer.
// ---------------------------------------------------------------------------
#define LDA 20  // 16 + 4 pad: stride%32==20 -> fragment loads conflict-free

__global__ __launch_bounds__(256)
void gemm_tn(const float* __restrict__ A, const float* __restrict__ B,
             float* __restrict__ C, int M, int N, int K) {
    __shared__ float As[2][128 * LDA];
    __shared__ float Bs[2][128 * LDA];

    const int tid = threadIdx.x;
    const int lane = tid & 31;
    const int warp = tid >> 5;
    const int gid = lane >> 2;   // 0..7
    const int tig = lane & 3;    // 0..3
    const int wm = warp & 3;     // 4 warps along M
    const int wn = warp >> 2;    // 2 warps along N
    const int m0 = blockIdx.y * 128;
    const int n0 = blockIdx.x * 128;

    float acc[2][8][4];
#pragma unroll
    for (int a = 0; a < 2; a++)
#pragma unroll
        for (int b = 0; b < 8; b++)
#pragma unroll
            for (int c = 0; c < 4; c++) acc[a][b][c] = 0.f;

    const int NT = K >> 4;

    auto issue = [&](int st, int kt) {
#pragma unroll
        for (int it = 0; it < 2; it++) {
            int L = tid + it * 256;       // 512 float4 units per tile
            int row = L >> 2;
            int kq = L & 3;
            __pipeline_memcpy_async(&As[st][row * LDA + kq * 4],
                                    &A[(size_t)(m0 + row) * K + kt * 16 + kq * 4], 16);
            __pipeline_memcpy_async(&Bs[st][row * LDA + kq * 4],
                                    &B[(size_t)(n0 + row) * K + kt * 16 + kq * 4], 16);
        }
        __pipeline_commit();
    };

    issue(0, 0);
    for (int kt = 0; kt < NT; kt++) {
        const int st = kt & 1;
        if (kt + 1 < NT) {
            issue(st ^ 1, kt + 1);
            __pipeline_wait_prior(1);
        } else {
            __pipeline_wait_prior(0);
        }
        __syncthreads();  // tile kt visible

#pragma unroll
        for (int kk = 0; kk < 16; kk += 8) {
            unsigned af[2][4];
#pragma unroll
            for (int mi = 0; mi < 2; mi++) {
                int r = wm * 32 + mi * 16;
                af[mi][0] = f2tf(As[st][(r + gid) * LDA + kk + tig]);
                af[mi][1] = f2tf(As[st][(r + gid + 8) * LDA + kk + tig]);
                af[mi][2] = f2tf(As[st][(r + gid) * LDA + kk + tig + 4]);
                af[mi][3] = f2tf(As[st][(r + gid + 8) * LDA + kk + tig + 4]);
            }
#pragma unroll
            for (int ni = 0; ni < 8; ni++) {
                unsigned bf[2];
                int nr = wn * 64 + ni * 8 + gid;
                bf[0] = f2tf(Bs[st][nr * LDA + kk + tig]);
                bf[1] = f2tf(Bs[st][nr * LDA + kk + tig + 4]);
                mma8(acc[0][ni], af[0], bf);
                mma8(acc[1][ni], af[1], bf);
            }
        }
        __syncthreads();  // compute done before next overwrite
    }

#pragma unroll
    for (int mi = 0; mi < 2; mi++) {
        int r0 = m0 + wm * 32 + mi * 16 + gid;
#pragma unroll
        for (int ni = 0; ni < 8; ni++) {
            int c0 = n0 + wn * 64 + ni * 8 + 2 * tig;
            *(float2*)&C[(size_t)r0 * N + c0] = make_float2(acc[mi][ni][0], acc[mi][ni][1]);
            *(float2*)&C[(size_t)(r0 + 8) * N + c0] = make_float2(acc[mi][ni][2], acc[mi][ni][3]);
        }
    }
}

// ---------------------------------------------------------------------------
// Sliding-window attention: one block = (b, h, 64-query tile).
// Window = 5 aligned key tiles of 64. S(64x320) in smem, full softmax,
// S = QK^T and O = PV via tf32 mma. Output written in [B,T,C] layout.
// ---------------------------------------------------------------------------
#define LQ 68   // Qs / Ks stride (A-side pattern: stride%32==4)
#define LV 72   // Vs stride       (B-side pattern: stride%32==8)
#define LS 324  // Ss stride       (A-side pattern: stride%32==4)

__global__ __launch_bounds__(256)
void attn_kernel() {
    extern __shared__ float sm[];
    float* Qs = sm;                       // 64*68
    float* KVs = Qs + 64 * LQ;            // 64*72
    float* Ss = KVs + 64 * LV;            // 64*324
    float* red = Ss + 64 * LS;            // 256
    float* rowSumInv = red + 256;         // 64

    const int tid = threadIdx.x;
    const int lane = tid & 31;
    const int warp = tid >> 5;
    const int gid = lane >> 2;
    const int tig = lane & 3;
    const int wm = warp & 3;   // 4 warps along queries
    const int wn = warp >> 2;  // 2 warps along keys / dd

    const int qt = blockIdx.x;
    const int bh = blockIdx.y;
    const int b = bh >> 3;
    const int h = bh & 7;
    const int qbase = qt * 64;
    const float* qkv = g_qkv + (size_t)b * TT * (3 * CC);
    const int hoff = h * DD;

    // Load Q tile (64x64)
#pragma unroll
    for (int it = 0; it < 4; it++) {
        int u = tid + it * 256;
        int row = u >> 4;
        int c4 = (u & 15) * 4;
        float4 v = *(const float4*)&qkv[(size_t)(qbase + row) * 1536 + hoff + c4];
        *(float4*)&Qs[row * LQ + c4] = v;
    }

    // ---------------- Phase A: scores ----------------
    for (int kt = 0; kt < 5; kt++) {
        const int kbase = qbase - MEMW + kt * 64;
        if (kbase >= 0) {
#pragma unroll
            for (int it = 0; it < 4; it++) {
                int u = tid + it * 256;
                int row = u >> 4;
                int c4 = (u & 15) * 4;
                float4 v = *(const float4*)&qkv[(size_t)(kbase + row) * 1536 + CC + hoff + c4];
                *(float4*)&KVs[row * LQ + c4] = v;
            }
        }
        __syncthreads();  // K (and Q on iter 0) visible

        if (kbase >= 0) {
            float sa[4][4];
#pragma unroll
            for (int ni = 0; ni < 4; ni++)
#pragma unroll
                for (int c = 0; c < 4; c++) sa[ni][c] = 0.f;

#pragma unroll
            for (int kk = 0; kk < 64; kk += 8) {
                unsigned af[4];
                int r = wm * 16;
                af[0] = f2tf(Qs[(r + gid) * LQ + kk + tig]);
                af[1] = f2tf(Qs[(r + gid + 8) * LQ + kk + tig]);
                af[2] = f2tf(Qs[(r + gid) * LQ + kk + tig + 4]);
                af[3] = f2tf(Qs[(r + gid + 8) * LQ + kk + tig + 4]);
#pragma unroll
                for (int ni = 0; ni < 4; ni++) {
                    unsigned bf[2];
                    int nr = wn * 32 + ni * 8 + gid;
                    bf[0] = f2tf(KVs[nr * LQ + kk + tig]);
                    bf[1] = f2tf(KVs[nr * LQ + kk + tig + 4]);
                    mma8(sa[ni], af, bf);
                }
            }
            // scale + mask + store to Ss
            int r0 = wm * 16 + gid;
            int i0 = qbase + r0, i1 = i0 + 8;
#pragma unroll
            for (int ni = 0; ni < 4; ni++) {
                int cl = wn * 32 + ni * 8 + 2 * tig;
                int j0 = kbase + cl, j1 = j0 + 1;
                bool m00 = (j0 <= i0) && (i0 - j0 <= MEMW);
                bool m01 = (j1 <= i0) && (i0 - j1 <= MEMW);
                bool m10 = (j0 <= i1) && (i1 - j0 <= MEMW);
                bool m11 = (j1 <= i1) && (i1 - j1 <= MEMW);
                Ss[r0 * LS + kt * 64 + cl]       = m00 ? sa[ni][0] * 0.125f : -1e30f;
                Ss[r0 * LS + kt * 64 + cl + 1]   = m01 ? sa[ni][1] * 0.125f : -1e30f;
                Ss[(r0 + 8) * LS + kt * 64 + cl]     = m10 ? sa[ni][2] * 0.125f : -1e30f;
                Ss[(r0 + 8) * LS + kt * 64 + cl + 1] = m11 ? sa[ni][3] * 0.125f : -1e30f;
            }
        } else {
            // out-of-range tile: fill with -inf-ish
#pragma unroll
            for (int it = 0; it < 16; it++) {
                int L = tid + it * 256;
                int row = L >> 6;
                int col = L & 63;
                Ss[row * LS + kt * 64 + col] = -1e30f;
            }
        }
        __syncthreads();  // tile done before KVs reload
    }

    // ---------------- Softmax (320 cols per row) ----------------
    {
        const int r = tid & 63;
        const int seg = tid >> 6;  // 4 segments x 80 cols
        const int cbeg = seg * 80, cend = cbeg + 80;
        float mx = -1e30f;
        for (int c = cbeg; c < cend; c++) mx = fmaxf(mx, Ss[r * LS + c]);
        red[seg * 64 + r] = mx;
        __syncthreads();
        float rmax = fmaxf(fmaxf(red[r], red[64 + r]), fmaxf(red[128 + r], red[192 + r]));
        __syncthreads();  // all reads of red done before reuse
        float ps = 0.f;
        for (int c = cbeg; c < cend; c++) {
            float e = __expf(Ss[r * LS + c] - rmax);
            Ss[r * LS + c] = e;
            ps += e;
        }
        red[seg * 64 + r] = ps;
        __syncthreads();
        if (tid < 64) {
            float s = red[tid] + red[64 + tid] + red[128 + tid] + red[192 + tid];
            rowSumInv[tid] = 1.0f / s;
        }
        __syncthreads();
    }

    // ---------------- Phase B: O = P @ V ----------------
    float oa[4][4];
#pragma unroll
    for (int ni = 0; ni < 4; ni++)
#pragma unroll
        for (int c = 0; c < 4; c++) oa[ni][c] = 0.f;

    for (int kt = 0; kt < 5; kt++) {
        const int kbase = qbase - MEMW + kt * 64;
        if (kbase >= 0) {
#pragma unroll
            for (int it = 0; it < 4; it++) {
                int u = tid + it * 256;
                int row = u >> 4;
                int c4 = (u & 15) * 4;
                float4 v = *(const float4*)&qkv[(size_t)(kbase + row) * 1536 + 2 * CC + hoff + c4];
                *(float4*)&KVs[row * LV + c4] = v;
            }
        }
        __syncthreads();

        if (kbase >= 0) {
#pragma unroll
            for (int kk = 0; kk < 64; kk += 8) {
                unsigned af[4];
                int r = wm * 16;
                int cb = kt * 64 + kk;
                af[0] = f2tf(Ss[(r + gid) * LS + cb + tig]);
                af[1] = f2tf(Ss[(r + gid + 8) * LS + cb + tig]);
                af[2] = f2tf(Ss[(r + gid) * LS + cb + tig + 4]);
                af[3] = f2tf(Ss[(r + gid + 8) * LS + cb + tig + 4]);
#pragma unroll
                for (int ni = 0; ni < 4; ni++) {
                    unsigned bf[2];
                    int nc = wn * 32 + ni * 8 + gid;
                    bf[0] = f2tf(KVs[(kk + tig) * LV + nc]);
                    bf[1] = f2tf(KVs[(kk + tig + 4) * LV + nc]);
                    mma8(oa[ni], af, bf);
                }
            }
        }
        __syncthreads();
    }

    // Normalize + write y in [B,T,C] layout: y[b][t][h*64 + dd]
    {
        int r0 = wm * 16 + gid;
        float inv0 = rowSumInv[r0];
        float inv1 = rowSumInv[r0 + 8];
#pragma unroll
        for (int ni = 0; ni < 4; ni++) {
            int cl = wn * 32 + ni * 8 + 2 * tig;
            float* y0 = g_y + ((size_t)b * TT + qbase + r0) * CC + hoff + cl;
            float* y1 = g_y + ((size_t)b * TT + qbase + r0 + 8) * CC + hoff + cl;
            y0[0] = oa[ni][0] * inv0;
            y0[1] = oa[ni][1] * inv0;
            y1[0] = oa[ni][2] * inv1;
            y1[1] = oa[ni][3] * inv1;
        }
    }
}

// ---------------------------------------------------------------------------
extern "C" void kernel_launch(void* const* d_in, const int* in_sizes, int n_in,
                              void* d_out, int out_size) {
    const float* x = (const float*)d_in[0];       // [B,T,C]
    const float* w_attn = (const float*)d_in[1];  // [3C,C]
    const float* w_proj = (const float*)d_in[2];  // [C,C]
    float* out = (float*)d_out;                   // [B,T,C]

    float* qkv = nullptr;
    float* y = nullptr;
    cudaGetSymbolAddress((void**)&qkv, g_qkv);
    cudaGetSymbolAddress((void**)&y, g_y);

    const int M = BB * TT;  // 8192

    // 1) QKV projection: qkv = x @ w_attn^T   [8192,1536]
    dim3 g1(3 * CC / 128, M / 128);
    gemm_tn<<<g1, 256>>>(x, w_attn, qkv, M, 3 * CC, CC);

    // 2) Sliding-window attention -> g_y [B,T,C]
    const int smemB = (64 * LQ + 64 * LV + 64 * LS + 256 + 64) * (int)sizeof(float);
    cudaFuncSetAttribute(attn_kernel, cudaFuncAttributeMaxDynamicSharedMemorySize, smemB);
    attn_kernel<<<dim3(TT / 64, BB * HH), 256, smemB>>>();

    // 3) Output projection: out = y @ w_proj^T   [8192,512]
    dim3 g2(CC / 128, M / 128);
    gemm_tn<<<g2, 256>>>(y, w_proj, out, M, CC, CC);
}

// round 13
// speedup vs baseline: 1.0076x; 1.0076x over previous
#include <cuda_runtime.h>
#include <cuda_pipeline.h>
#include <cstdint>

// Problem constants
#define BB 2
#define TT 4096
#define CC 512
#define HH 8
#define DD 64
#define MEMW 256

// Scratch (allocation-free rule: device globals)
__device__ float g_qkv[(size_t)BB * TT * 3 * CC];  // 50.3 MB
__device__ float g_y[(size_t)BB * TT * CC];        // 16.8 MB

__device__ __forceinline__ unsigned f2tf(float x) {
    unsigned r;
    asm("cvt.rna.tf32.f32 %0, %1;" : "=r"(r) : "f"(x));
    return r;
}

__device__ __forceinline__ void mma8(float* d, const unsigned* a, const unsigned* b) {
    asm volatile(
        "mma.sync.aligned.m16n8k8.row.col.f32.tf32.tf32.f32 "
        "{%0,%1,%2,%3},{%4,%5,%6,%7},{%8,%9},{%0,%1,%2,%3};\n"
        : "+f"(d[0]), "+f"(d[1]), "+f"(d[2]), "+f"(d[3])
        : "r"(a[0]), "r"(a[1]), "r"(a[2]), "r"(a[3]), "r"(b[0]), "r"(b[1]));
}

// ---------------------------------------------------------------------------
// GEMM: C[M,N] = A[M,K] * B[N,K]^T   (A row-major MxK, B row-major NxK)
// Block tile 128x128, k-tile 16, cp.async double buffer.
// ---------------------------------------------------------------------------
#define LDA 20  // 16 + 4 pad: stride%32==20 -> fragment loads conflict-free

__global__ __launch_bounds__(256)
void gemm_tn(const float* __restrict__ A, const float* __restrict__ B,
             float* __restrict__ C, int M, int N, int K) {
    __shared__ float As[2][128 * LDA];
    __shared__ float Bs[2][128 * LDA];

    const int tid = threadIdx.x;
    const int lane = tid & 31;
    const int warp = tid >> 5;
    const int gid = lane >> 2;   // 0..7
    const int tig = lane & 3;    // 0..3
    const int wm = warp & 3;     // 4 warps along M
    const int wn = warp >> 2;    // 2 warps along N
    const int m0 = blockIdx.y * 128;
    const int n0 = blockIdx.x * 128;

    float acc[2][8][4];
#pragma unroll
    for (int a = 0; a < 2; a++)
#pragma unroll
        for (int b = 0; b < 8; b++)
#pragma unroll
            for (int c = 0; c < 4; c++) acc[a][b][c] = 0.f;

    const int NT = K >> 4;

    auto issue = [&](int st, int kt) {
#pragma unroll
        for (int it = 0; it < 2; it++) {
            int L = tid + it * 256;       // 512 float4 units per tile
            int row = L >> 2;
            int kq = L & 3;
            __pipeline_memcpy_async(&As[st][row * LDA + kq * 4],
                                    &A[(size_t)(m0 + row) * K + kt * 16 + kq * 4], 16);
            __pipeline_memcpy_async(&Bs[st][row * LDA + kq * 4],
                                    &B[(size_t)(n0 + row) * K + kt * 16 + kq * 4], 16);
        }
        __pipeline_commit();
    };

    issue(0, 0);
    for (int kt = 0; kt < NT; kt++) {
        const int st = kt & 1;
        if (kt + 1 < NT) {
            issue(st ^ 1, kt + 1);
            __pipeline_wait_prior(1);
        } else {
            __pipeline_wait_prior(0);
        }
        __syncthreads();  // tile kt visible

#pragma unroll
        for (int kk = 0; kk < 16; kk += 8) {
            unsigned af[2][4];
#pragma unroll
            for (int mi = 0; mi < 2; mi++) {
                int r = wm * 32 + mi * 16;
                af[mi][0] = f2tf(As[st][(r + gid) * LDA + kk + tig]);
                af[mi][1] = f2tf(As[st][(r + gid + 8) * LDA + kk + tig]);
                af[mi][2] = f2tf(As[st][(r + gid) * LDA + kk + tig + 4]);
                af[mi][3] = f2tf(As[st][(r + gid + 8) * LDA + kk + tig + 4]);
            }
#pragma unroll
            for (int ni = 0; ni < 8; ni++) {
                unsigned bf[2];
                int nr = wn * 64 + ni * 8 + gid;
                bf[0] = f2tf(Bs[st][nr * LDA + kk + tig]);
                bf[1] = f2tf(Bs[st][nr * LDA + kk + tig + 4]);
                mma8(acc[0][ni], af[0], bf);
                mma8(acc[1][ni], af[1], bf);
            }
        }
        __syncthreads();  // compute done before next overwrite
    }

#pragma unroll
    for (int mi = 0; mi < 2; mi++) {
        int r0 = m0 + wm * 32 + mi * 16 + gid;
#pragma unroll
        for (int ni = 0; ni < 8; ni++) {
            int c0 = n0 + wn * 64 + ni * 8 + 2 * tig;
            *(float2*)&C[(size_t)r0 * N + c0] = make_float2(acc[mi][ni][0], acc[mi][ni][1]);
            *(float2*)&C[(size_t)(r0 + 8) * N + c0] = make_float2(acc[mi][ni][2], acc[mi][ni][3]);
        }
    }
}

// ---------------------------------------------------------------------------
// Sliding-window attention: one block = (b, h, 64-query tile).
// Window = 5 aligned key tiles of 64. S(64x320) in smem, full softmax,
// S = QK^T and O = PV via tf32 mma. Output written in [B,T,C] layout.
// ---------------------------------------------------------------------------
#define LQ 68   // Qs / Ks stride (A-side pattern: stride%32==4)
#define LV 72   // Vs stride       (B-side pattern: stride%32==8)
#define LS 324  // Ss stride       (A-side pattern: stride%32==4)

__global__ __launch_bounds__(256)
void attn_kernel() {
    extern __shared__ float sm[];
    float* Qs = sm;                       // 64*68
    float* KVs = Qs + 64 * LQ;            // 64*72
    float* Ss = KVs + 64 * LV;            // 64*324
    float* red = Ss + 64 * LS;            // 256
    float* rowSumInv = red + 256;         // 64

    const int tid = threadIdx.x;
    const int lane = tid & 31;
    const int warp = tid >> 5;
    const int gid = lane >> 2;
    const int tig = lane & 3;
    const int wm = warp & 3;   // 4 warps along queries
    const int wn = warp >> 2;  // 2 warps along keys / dd

    const int qt = blockIdx.x;
    const int bh = blockIdx.y;
    const int b = bh >> 3;
    const int h = bh & 7;
    const int qbase = qt * 64;
    const float* qkv = g_qkv + (size_t)b * TT * (3 * CC);
    const int hoff = h * DD;

    // Load Q tile (64x64)
#pragma unroll
    for (int it = 0; it < 4; it++) {
        int u = tid + it * 256;
        int row = u >> 4;
        int c4 = (u & 15) * 4;
        float4 v = *(const float4*)&qkv[(size_t)(qbase + row) * 1536 + hoff + c4];
        *(float4*)&Qs[row * LQ + c4] = v;
    }

    // ---------------- Phase A: scores ----------------
    for (int kt = 0; kt < 5; kt++) {
        const int kbase = qbase - MEMW + kt * 64;
        if (kbase >= 0) {
#pragma unroll
            for (int it = 0; it < 4; it++) {
                int u = tid + it * 256;
                int row = u >> 4;
                int c4 = (u & 15) * 4;
                float4 v = *(const float4*)&qkv[(size_t)(kbase + row) * 1536 + CC + hoff + c4];
                *(float4*)&KVs[row * LQ + c4] = v;
            }
        }
        __syncthreads();  // K (and Q on iter 0) visible

        if (kbase >= 0) {
            float sa[4][4];
#pragma unroll
            for (int ni = 0; ni < 4; ni++)
#pragma unroll
                for (int c = 0; c < 4; c++) sa[ni][c] = 0.f;

#pragma unroll
            for (int kk = 0; kk < 64; kk += 8) {
                unsigned af[4];
                int r = wm * 16;
                af[0] = f2tf(Qs[(r + gid) * LQ + kk + tig]);
                af[1] = f2tf(Qs[(r + gid + 8) * LQ + kk + tig]);
                af[2] = f2tf(Qs[(r + gid) * LQ + kk + tig + 4]);
                af[3] = f2tf(Qs[(r + gid + 8) * LQ + kk + tig + 4]);
#pragma unroll
                for (int ni = 0; ni < 4; ni++) {
                    unsigned bf[2];
                    int nr = wn * 32 + ni * 8 + gid;
                    bf[0] = f2tf(KVs[nr * LQ + kk + tig]);
                    bf[1] = f2tf(KVs[nr * LQ + kk + tig + 4]);
                    mma8(sa[ni], af, bf);
                }
            }
            // scale + mask + store to Ss
            int r0 = wm * 16 + gid;
            int i0 = qbase + r0, i1 = i0 + 8;
#pragma unroll
            for (int ni = 0; ni < 4; ni++) {
                int cl = wn * 32 + ni * 8 + 2 * tig;
                int j0 = kbase + cl, j1 = j0 + 1;
                bool m00 = (j0 <= i0) && (i0 - j0 <= MEMW);
                bool m01 = (j1 <= i0) && (i0 - j1 <= MEMW);
                bool m10 = (j0 <= i1) && (i1 - j0 <= MEMW);
                bool m11 = (j1 <= i1) && (i1 - j1 <= MEMW);
                Ss[r0 * LS + kt * 64 + cl]       = m00 ? sa[ni][0] * 0.125f : -1e30f;
                Ss[r0 * LS + kt * 64 + cl + 1]   = m01 ? sa[ni][1] * 0.125f : -1e30f;
                Ss[(r0 + 8) * LS + kt * 64 + cl]     = m10 ? sa[ni][2] * 0.125f : -1e30f;
                Ss[(r0 + 8) * LS + kt * 64 + cl + 1] = m11 ? sa[ni][3] * 0.125f : -1e30f;
            }
        } else {
            // out-of-range tile: fill with -inf-ish
#pragma unroll
            for (int it = 0; it < 16; it++) {
                int L = tid + it * 256;
                int row = L >> 6;
                int col = L & 63;
                Ss[row * LS + kt * 64 + col] = -1e30f;
            }
        }
        __syncthreads();  // tile done before KVs reload
    }

    // ---------------- Softmax (320 cols per row) ----------------
    {
        const int r = tid & 63;
        const int seg = tid >> 6;  // 4 segments x 80 cols
        const int cbeg = seg * 80, cend = cbeg + 80;
        float mx = -1e30f;
        for (int c = cbeg; c < cend; c++) mx = fmaxf(mx, Ss[r * LS + c]);
        red[seg * 64 + r] = mx;
        __syncthreads();
        float rmax = fmaxf(fmaxf(red[r], red[64 + r]), fmaxf(red[128 + r], red[192 + r]));
        __syncthreads();  // all reads of red done before reuse
        float ps = 0.f;
        for (int c = cbeg; c < cend; c++) {
            float e = __expf(Ss[r * LS + c] - rmax);
            Ss[r * LS + c] = e;
            ps += e;
        }
        red[seg * 64 + r] = ps;
        __syncthreads();
        if (tid < 64) {
            float s = red[tid] + red[64 + tid] + red[128 + tid] + red[192 + tid];
            rowSumInv[tid] = 1.0f / s;
        }
        __syncthreads();
    }

    // ---------------- Phase B: O = P @ V ----------------
    float oa[4][4];
#pragma unroll
    for (int ni = 0; ni < 4; ni++)
#pragma unroll
        for (int c = 0; c < 4; c++) oa[ni][c] = 0.f;

    for (int kt = 0; kt < 5; kt++) {
        const int kbase = qbase - MEMW + kt * 64;
        if (kbase >= 0) {
#pragma unroll
            for (int it = 0; it < 4; it++) {
                int u = tid + it * 256;
                int row = u >> 4;
                int c4 = (u & 15) * 4;
                float4 v = *(const float4*)&qkv[(size_t)(kbase + row) * 1536 + 2 * CC + hoff + c4];
                *(float4*)&KVs[row * LV + c4] = v;
            }
        }
        __syncthreads();

        if (kbase >= 0) {
#pragma unroll
            for (int kk = 0; kk < 64; kk += 8) {
                unsigned af[4];
                int r = wm * 16;
                int cb = kt * 64 + kk;
                af[0] = f2tf(Ss[(r + gid) * LS + cb + tig]);
                af[1] = f2tf(Ss[(r + gid + 8) * LS + cb + tig]);
                af[2] = f2tf(Ss[(r + gid) * LS + cb + tig + 4]);
                af[3] = f2tf(Ss[(r + gid + 8) * LS + cb + tig + 4]);
#pragma unroll
                for (int ni = 0; ni < 4; ni++) {
                    unsigned bf[2];
                    int nc = wn * 32 + ni * 8 + gid;
                    bf[0] = f2tf(KVs[(kk + tig) * LV + nc]);
                    bf[1] = f2tf(KVs[(kk + tig + 4) * LV + nc]);
                    mma8(oa[ni], af, bf);
                }
            }
        }
        __syncthreads();
    }

    // Normalize + write y in [B,T,C] layout: y[b][t][h*64 + dd]
    {
        int r0 = wm * 16 + gid;
        float inv0 = rowSumInv[r0];
        float inv1 = rowSumInv[r0 + 8];
#pragma unroll
        for (int ni = 0; ni < 4; ni++) {
            int cl = wn * 32 + ni * 8 + 2 * tig;
            float* y0 = g_y + ((size_t)b * TT + qbase + r0) * CC + hoff + cl;
            float* y1 = g_y + ((size_t)b * TT + qbase + r0 + 8) * CC + hoff + cl;
            y0[0] = oa[ni][0] * inv0;
            y0[1] = oa[ni][1] * inv0;
            y1[0] = oa[ni][2] * inv1;
            y1[1] = oa[ni][3] * inv1;
        }
    }
}

// ---------------------------------------------------------------------------
extern "C" void kernel_launch(void* const* d_in, const int* in_sizes, int n_in,
                              void* d_out, int out_size) {
    const float* x = (const float*)d_in[0];       // [B,T,C]
    const float* w_attn = (const float*)d_in[1];  // [3C,C]
    const float* w_proj = (const float*)d_in[2];  // [C,C]
    float* out = (float*)d_out;                   // [B,T,C]

    float* qkv = nullptr;
    float* y = nullptr;
    cudaGetSymbolAddress((void**)&qkv, g_qkv);
    cudaGetSymbolAddress((void**)&y, g_y);

    const int M = BB * TT;  // 8192

    // 1) QKV projection: qkv = x @ w_attn^T   [8192,1536]
    dim3 g1(3 * CC / 128, M / 128);
    gemm_tn<<<g1, 256>>>(x, w_attn, qkv, M, 3 * CC, CC);

    // 2) Sliding-window attention -> g_y [B,T,C]
    const int smemB = (64 * LQ + 64 * LV + 64 * LS + 256 + 64) * (int)sizeof(float);
    cudaFuncSetAttribute(attn_kernel, cudaFuncAttributeMaxDynamicSharedMemorySize, smemB);
    attn_kernel<<<dim3(TT / 64, BB * HH), 256, smemB>>>();

    // 3) Output projection: out = y @ w_proj^T   [8192,512]
    dim3 g2(CC / 128, M / 128);
    gemm_tn<<<g2, 256>>>(y, w_proj, out, M, CC, CC);
}

// round 16
// speedup vs baseline: 1.0214x; 1.0137x over previous
#include <cuda_runtime.h>
#include <cuda_pipeline.h>
#include <cstdint>

// Problem constants
#define BB 2
#define TT 4096
#define CC 512
#define HH 8
#define DD 64
#define MEMW 256

// Scratch (allocation-free rule: device globals)
__device__ float g_qkv[(size_t)BB * TT * 3 * CC];  // 50.3 MB
__device__ float g_y[(size_t)BB * TT * CC];        // 16.8 MB

__device__ __forceinline__ unsigned f2tf(float x) {
    unsigned r;
    asm("cvt.rna.tf32.f32 %0, %1;" : "=r"(r) : "f"(x));
    return r;
}
__device__ __forceinline__ float roundtf(float x) {
    return __uint_as_float(f2tf(x));
}

__device__ __forceinline__ void mma8(float* d, const unsigned* a, const unsigned* b) {
    asm volatile(
        "mma.sync.aligned.m16n8k8.row.col.f32.tf32.tf32.f32 "
        "{%0,%1,%2,%3},{%4,%5,%6,%7},{%8,%9},{%0,%1,%2,%3};\n"
        : "+f"(d[0]), "+f"(d[1]), "+f"(d[2]), "+f"(d[3])
        : "r"(a[0]), "r"(a[1]), "r"(a[2]), "r"(a[3]), "r"(b[0]), "r"(b[1]));
}

// ---------------------------------------------------------------------------
// GEMM: C[M,N] = A[M,K] * B[N,K]^T
// Block tile 128x128, 4 warps (64x64 warp tiles), k-tile 16,
// 3-stage cp.async ring, one __syncthreads per k-tile, 2 blocks/SM.
// ---------------------------------------------------------------------------
#define LDA 20         // 16 + 4 pad: gid*20 mod 32 covers all 8 groups -> conflict-free
#define GSTG 3         // pipeline stages
#define GTILE (128 * LDA)

__global__ __launch_bounds__(128, 2)
void gemm_tn(const float* __restrict__ A, const float* __restrict__ B,
             float* __restrict__ C, int M, int N, int K) {
    extern __shared__ float sh[];  // GSTG * 2 * GTILE floats

    const int tid = threadIdx.x;
    const int lane = tid & 31;
    const int warp = tid >> 5;   // 0..3
    const int gid = lane >> 2;   // 0..7
    const int tig = lane & 3;    // 0..3
    const int wm = warp & 1;     // 2 warps along M
    const int wn = warp >> 1;    // 2 warps along N
    const int m0 = blockIdx.y * 128;
    const int n0 = blockIdx.x * 128;

    float acc[4][8][4];
#pragma unroll
    for (int a = 0; a < 4; a++)
#pragma unroll
        for (int b = 0; b < 8; b++)
#pragma unroll
            for (int c = 0; c < 4; c++) acc[a][b][c] = 0.f;

    const int NT = K >> 4;

    auto issue = [&](int st, int kt) {
        float* As = sh + st * (2 * GTILE);
        float* Bs = As + GTILE;
#pragma unroll
        for (int it = 0; it < 4; it++) {
            int L = tid + it * 128;       // 512 float4 units per tile
            int row = L >> 2;
            int kq = L & 3;
            __pipeline_memcpy_async(&As[row * LDA + kq * 4],
                                    &A[(size_t)(m0 + row) * K + kt * 16 + kq * 4], 16);
            __pipeline_memcpy_async(&Bs[row * LDA + kq * 4],
                                    &B[(size_t)(n0 + row) * K + kt * 16 + kq * 4], 16);
        }
        __pipeline_commit();
    };

    issue(0, 0);
    issue(1, 1);  // NT >= 2 always here (K=512)

    int st = 0;
    for (int kt = 0; kt < NT; kt++) {
        if (kt + 1 < NT) __pipeline_wait_prior(1);
        else __pipeline_wait_prior(0);
        __syncthreads();  // tile kt visible to all; compute kt-1 finished by all

        if (kt + 2 < NT) {
            int wst = st + 2; if (wst >= GSTG) wst -= GSTG;
            issue(wst, kt + 2);
        }

        const float* As = sh + st * (2 * GTILE);
        const float* Bs = As + GTILE;

#pragma unroll
        for (int kk = 0; kk < 16; kk += 8) {
            unsigned af[4][4];
#pragma unroll
            for (int mi = 0; mi < 4; mi++) {
                int r = wm * 64 + mi * 16;
                af[mi][0] = f2tf(As[(r + gid) * LDA + kk + tig]);
                af[mi][1] = f2tf(As[(r + gid + 8) * LDA + kk + tig]);
                af[mi][2] = f2tf(As[(r + gid) * LDA + kk + tig + 4]);
                af[mi][3] = f2tf(As[(r + gid + 8) * LDA + kk + tig + 4]);
            }
#pragma unroll
            for (int ni = 0; ni < 8; ni++) {
                unsigned bf[2];
                int nr = wn * 64 + ni * 8 + gid;
                bf[0] = f2tf(Bs[nr * LDA + kk + tig]);
                bf[1] = f2tf(Bs[nr * LDA + kk + tig + 4]);
#pragma unroll
                for (int mi = 0; mi < 4; mi++) mma8(acc[mi][ni], af[mi], bf);
            }
        }
        if (++st == GSTG) st = 0;
    }

#pragma unroll
    for (int mi = 0; mi < 4; mi++) {
        int r0 = m0 + wm * 64 + mi * 16 + gid;
#pragma unroll
        for (int ni = 0; ni < 8; ni++) {
            int c0 = n0 + wn * 64 + ni * 8 + 2 * tig;
            *(float2*)&C[(size_t)r0 * N + c0] = make_float2(acc[mi][ni][0], acc[mi][ni][1]);
            *(float2*)&C[(size_t)(r0 + 8) * N + c0] = make_float2(acc[mi][ni][2], acc[mi][ni][3]);
        }
    }
}

// ---------------------------------------------------------------------------
// Sliding-window attention: one block = (b, h, 64-query tile).
// Window = up to 5 aligned key tiles of 64. S(64x320) in smem.
// tf32 rounding happens once at staging (STS) time; inner loops are LDS+mma.
// Softmax iterates only the valid window per row; invalid cols zero-filled.
// Register prefetch of next K/V tile overlaps LDG with mma.
// ---------------------------------------------------------------------------
#define LQ 68   // Qs / Ks stride
#define LV 72   // Vs stride
#define LS 324  // Ss stride

__global__ __launch_bounds__(256)
void attn_kernel() {
    extern __shared__ float sm[];
    float* Qs = sm;                       // 64*68
    float* KVs = Qs + 64 * LQ;            // 64*72
    float* Ss = KVs + 64 * LV;            // 64*324
    float* red = Ss + 64 * LS;            // 256
    float* rowSumInv = red + 256;         // 64

    const int tid = threadIdx.x;
    const int lane = tid & 31;
    const int warp = tid >> 5;
    const int gid = lane >> 2;
    const int tig = lane & 3;
    const int wm = warp & 3;   // 4 warps along queries
    const int wn = warp >> 2;  // 2 warps along keys / dd

    const int qt = blockIdx.x;
    const int bh = blockIdx.y;
    const int b = bh >> 3;
    const int h = bh & 7;
    const int qbase = qt * 64;
    const float* qkv = g_qkv + (size_t)b * TT * (3 * CC);
    const int hoff = h * DD;

    const int ldrow = tid >> 4;          // staging row (64 rows, 4 iters)
    const int ldc4 = (tid & 15) * 4;     // staging col

    // Load Q tile (64x64), rounded to tf32 at store
#pragma unroll
    for (int it = 0; it < 4; it++) {
        int row = ldrow + it * 16;
        float4 v = *(const float4*)&qkv[(size_t)(qbase + row) * 1536 + hoff + ldc4];
        v.x = roundtf(v.x); v.y = roundtf(v.y); v.z = roundtf(v.z); v.w = roundtf(v.w);
        *(float4*)&Qs[row * LQ + ldc4] = v;
    }

    const int kt0 = (qt < 4) ? (4 - qt) : 0;  // first valid key tile

    // ---------------- Phase A: scores ----------------
    float4 stage[4];
    {
        const int kbase = qbase - MEMW + kt0 * 64;
#pragma unroll
        for (int it = 0; it < 4; it++)
            stage[it] = *(const float4*)&qkv[(size_t)(kbase + ldrow + it * 16) * 1536 + CC + hoff + ldc4];
    }

    for (int kt = kt0; kt < 5; kt++) {
        __syncthreads();  // prior mma done reading KVs (and Qs stores visible)
#pragma unroll
        for (int it = 0; it < 4; it++) {
            float4 v = stage[it];
            v.x = roundtf(v.x); v.y = roundtf(v.y); v.z = roundtf(v.z); v.w = roundtf(v.w);
            *(float4*)&KVs[(ldrow + it * 16) * LQ + ldc4] = v;
        }
        if (kt + 1 < 5) {
            const int kbase = qbase - MEMW + (kt + 1) * 64;
#pragma unroll
            for (int it = 0; it < 4; it++)
                stage[it] = *(const float4*)&qkv[(size_t)(kbase + ldrow + it * 16) * 1536 + CC + hoff + ldc4];
        }
        __syncthreads();  // K tile visible

        float sa[4][4];
#pragma unroll
        for (int ni = 0; ni < 4; ni++)
#pragma unroll
            for (int c = 0; c < 4; c++) sa[ni][c] = 0.f;

#pragma unroll
        for (int kk = 0; kk < 64; kk += 8) {
            unsigned af[4];
            int r = wm * 16;
            af[0] = __float_as_uint(Qs[(r + gid) * LQ + kk + tig]);
            af[1] = __float_as_uint(Qs[(r + gid + 8) * LQ + kk + tig]);
            af[2] = __float_as_uint(Qs[(r + gid) * LQ + kk + tig + 4]);
            af[3] = __float_as_uint(Qs[(r + gid + 8) * LQ + kk + tig + 4]);
#pragma unroll
            for (int ni = 0; ni < 4; ni++) {
                unsigned bf[2];
                int nr = wn * 32 + ni * 8 + gid;
                bf[0] = __float_as_uint(KVs[nr * LQ + kk + tig]);
                bf[1] = __float_as_uint(KVs[nr * LQ + kk + tig + 4]);
                mma8(sa[ni], af, bf);
            }
        }
        // raw score store (no masking — softmax handles validity)
        int r0 = wm * 16 + gid;
#pragma unroll
        for (int ni = 0; ni < 4; ni++) {
            int cl = kt * 64 + wn * 32 + ni * 8 + 2 * tig;
            Ss[r0 * LS + cl] = sa[ni][0] * 0.125f;
            Ss[r0 * LS + cl + 1] = sa[ni][1] * 0.125f;
            Ss[(r0 + 8) * LS + cl] = sa[ni][2] * 0.125f;
            Ss[(r0 + 8) * LS + cl + 1] = sa[ni][3] * 0.125f;
        }
    }

    // Prefetch first V tile during softmax
    {
        const int kbase = qbase - MEMW + kt0 * 64;
#pragma unroll
        for (int it = 0; it < 4; it++)
            stage[it] = *(const float4*)&qkv[(size_t)(kbase + ldrow + it * 16) * 1536 + 2 * CC + hoff + ldc4];
    }
    __syncthreads();  // all Ss writes visible

    // ---------------- Softmax over valid window [lo, hi) per row ----------------
    {
        const int r = tid & 63;
        const int seg = tid >> 6;  // 4 threads per row
        const int guard = MEMW - qbase;               // j >= 0 constraint
        const int lo = (r > guard) ? r : guard;       // max(r, 256-qbase)
        const int hi = r + MEMW + 1;                  // r + 257 (<= 320)
        const int vlen = hi - lo;
        const int vq = (vlen + 3) >> 2;
        const int cb = lo + seg * vq;
        int ce = lo + (seg + 1) * vq; if (ce > hi) ce = hi;

        float mx = -1e30f;
        for (int c = cb; c < ce; c++) mx = fmaxf(mx, Ss[r * LS + c]);
        red[seg * 64 + r] = mx;
        __syncthreads();
        float rmax = fmaxf(fmaxf(red[r], red[64 + r]), fmaxf(red[128 + r], red[192 + r]));
        __syncthreads();  // all reads of red done before reuse

        float ps = 0.f;
        for (int c = cb; c < ce; c++) {
            float e = __expf(Ss[r * LS + c] - rmax);
            Ss[r * LS + c] = roundtf(e);  // pre-rounded P for the PV mma
            ps += e;
        }
        // zero-fill invalid cols: [0, lo) U [hi, 320)
        const int zlen = lo + (320 - hi);
        const int zq = (zlen + 3) >> 2;
        int zb = seg * zq;
        int zend = zb + zq; if (zend > zlen) zend = zlen;
        for (int z = zb; z < zend; z++) {
            int c = (z < lo) ? z : (hi + z - lo);
            Ss[r * LS + c] = 0.f;
        }
        red[seg * 64 + r] = ps;
        __syncthreads();
        if (tid < 64) {
            float s = red[tid] + red[64 + tid] + red[128 + tid] + red[192 + tid];
            rowSumInv[tid] = 1.0f / s;
        }
    }

    // ---------------- Phase B: O = P @ V ----------------
    float oa[4][4];
#pragma unroll
    for (int ni = 0; ni < 4; ni++)
#pragma unroll
        for (int c = 0; c < 4; c++) oa[ni][c] = 0.f;

    for (int kt = kt0; kt < 5; kt++) {
        __syncthreads();  // prior mma done with KVs; softmax Ss writes visible (first iter)
#pragma unroll
        for (int it = 0; it < 4; it++) {
            float4 v = stage[it];
            v.x = roundtf(v.x); v.y = roundtf(v.y); v.z = roundtf(v.z); v.w = roundtf(v.w);
            *(float4*)&KVs[(ldrow + it * 16) * LV + ldc4] = v;
        }
        if (kt + 1 < 5) {
            const int kbase = qbase - MEMW + (kt + 1) * 64;
#pragma unroll
            for (int it = 0; it < 4; it++)
                stage[it] = *(const float4*)&qkv[(size_t)(kbase + ldrow + it * 16) * 1536 + 2 * CC + hoff + ldc4];
        }
        __syncthreads();  // V tile visible

#pragma unroll
        for (int kk = 0; kk < 64; kk += 8) {
            unsigned af[4];
            int r = wm * 16;
            int cbx = kt * 64 + kk;
            af[0] = __float_as_uint(Ss[(r + gid) * LS + cbx + tig]);
            af[1] = __float_as_uint(Ss[(r + gid + 8) * LS + cbx + tig]);
            af[2] = __float_as_uint(Ss[(r + gid) * LS + cbx + tig + 4]);
            af[3] = __float_as_uint(Ss[(r + gid + 8) * LS + cbx + tig + 4]);
#pragma unroll
            for (int ni = 0; ni < 4; ni++) {
                unsigned bf[2];
                int nc = wn * 32 + ni * 8 + gid;
                bf[0] = __float_as_uint(KVs[(kk + tig) * LV + nc]);
                bf[1] = __float_as_uint(KVs[(kk + tig + 4) * LV + nc]);
                mma8(oa[ni], af, bf);
            }
        }
    }

    // Normalize + write y in [B,T,C] layout
    {
        int r0 = wm * 16 + gid;
        float inv0 = rowSumInv[r0];
        float inv1 = rowSumInv[r0 + 8];
#pragma unroll
        for (int ni = 0; ni < 4; ni++) {
            int cl = wn * 32 + ni * 8 + 2 * tig;
            float* y0 = g_y + ((size_t)b * TT + qbase + r0) * CC + hoff + cl;
            float* y1 = g_y + ((size_t)b * TT + qbase + r0 + 8) * CC + hoff + cl;
            y0[0] = oa[ni][0] * inv0;
            y0[1] = oa[ni][1] * inv0;
            y1[0] = oa[ni][2] * inv1;
            y1[1] = oa[ni][3] * inv1;
        }
    }
}

// ---------------------------------------------------------------------------
extern "C" void kernel_launch(void* const* d_in, const int* in_sizes, int n_in,
                              void* d_out, int out_size) {
    const float* x = (const float*)d_in[0];       // [B,T,C]
    const float* w_attn = (const float*)d_in[1];  // [3C,C]
    const float* w_proj = (const float*)d_in[2];  // [C,C]
    float* out = (float*)d_out;                   // [B,T,C]

    float* qkv = nullptr;
    float* y = nullptr;
    cudaGetSymbolAddress((void**)&qkv, g_qkv);
    cudaGetSymbolAddress((void**)&y, g_y);

    const int M = BB * TT;  // 8192

    const int gemmSmem = GSTG * 2 * GTILE * (int)sizeof(float);  // 61440
    cudaFuncSetAttribute(gemm_tn, cudaFuncAttributeMaxDynamicSharedMemorySize, gemmSmem);

    // 1) QKV projection: qkv = x @ w_attn^T   [8192,1536]
    dim3 g1(3 * CC / 128, M / 128);
    gemm_tn<<<g1, 128, gemmSmem>>>(x, w_attn, qkv, M, 3 * CC, CC);

    // 2) Sliding-window attention -> g_y [B,T,C]
    const int smemB = (64 * LQ + 64 * LV + 64 * LS + 256 + 64) * (int)sizeof(float);
    cudaFuncSetAttribute(attn_kernel, cudaFuncAttributeMaxDynamicSharedMemorySize, smemB);
    attn_kernel<<<dim3(TT / 64, BB * HH), 256, smemB>>>();

    // 3) Output projection: out = y @ w_proj^T   [8192,512]
    dim3 g2(CC / 128, M / 128);
    gemm_tn<<<g2, 128, gemmSmem>>>(y, w_proj, out, M, CC, CC);
}